// round 1
// baseline (speedup 1.0000x reference)
#include <cuda_runtime.h>
#include <cstdint>

// Problem dims
#define NB    16
#define NPOS  4096
#define CIN   512
#define DIMD  256          // DIM == VDIM == 256
#define NTOT  (NB*NPOS)    // 65536
#define NSPLIT 8

// GEMM tiles
#define BM 128
#define BN 128
#define BK 32
#define LDA 36    // k-contiguous layout row length (BK=32 + 4 pad)
#define LDB 136   // mn-contiguous layout row length (BN=128 + 8 pad)

// ---------------- scratch (device globals; no malloc allowed) ----------------
__device__ float g_q[(size_t)NTOT*DIMD];
__device__ float g_k[(size_t)NTOT*DIMD];
__device__ float g_v[(size_t)NTOT*DIMD];
__device__ float g_kmax[NB*DIMD];
__device__ float g_krs [NB*DIMD];
__device__ float g_vmax[NB*DIMD];
__device__ float g_vrs [NB*DIMD];
__device__ float g_gdp[(size_t)NSPLIT*NB*DIMD*DIMD];
__device__ float g_gd [(size_t)NB*DIMD*DIMD];
__device__ float g_Mm [(size_t)NB*DIMD*CIN];

// ---------------- helpers ----------------
__device__ __forceinline__ float exp_fast(float x) {
    // e^x = 2^(x*log2e); FMA-only (avoid MUFU throughput wall)
    float t = x * 1.4426950408889634f;
    t = fminf(fmaxf(t, -120.f), 120.f);
    float fi = rintf(t);
    float f  = t - fi;                       // [-0.5, 0.5]
    float p = 1.3333558146e-3f;
    p = fmaf(p, f, 9.6181291076e-3f);
    p = fmaf(p, f, 5.5504108665e-2f);
    p = fmaf(p, f, 2.4022650696e-1f);
    p = fmaf(p, f, 6.9314718056e-1f);
    p = fmaf(p, f, 1.0f);
    return __int_as_float(((int)fi + 127) << 23) * p;
}

__device__ __forceinline__ float tf32r(float x) {
    uint32_t u;
    asm("cvt.rna.tf32.f32 %0, %1;" : "=r"(u) : "f"(x));
    return __uint_as_float(u);
}

__device__ __forceinline__ void mma8(float* d, const float* a, const float* b) {
    asm volatile(
        "mma.sync.aligned.m16n8k8.row.col.f32.tf32.tf32.f32 "
        "{%0,%1,%2,%3},{%4,%5,%6,%7},{%8,%9},{%0,%1,%2,%3};\n"
        : "+f"(d[0]), "+f"(d[1]), "+f"(d[2]), "+f"(d[3])
        : "r"(__float_as_uint(a[0])), "r"(__float_as_uint(a[1])),
          "r"(__float_as_uint(a[2])), "r"(__float_as_uint(a[3])),
          "r"(__float_as_uint(b[0])), "r"(__float_as_uint(b[1])));
}

// ---------------- tile loaders ----------------
// KC: operand element (mn, k) at smem[mn*LDA + k]; src row-major [mn][k], ld given
__device__ __forceinline__ void load_KC(float* As, const float* src, int ld) {
    int tid = threadIdx.x;
#pragma unroll
    for (int i = 0; i < 4; i++) {
        int idx = tid + i * 256;
        int m = idx >> 3;
        int kq = (idx & 7) << 2;
        float4 u = *reinterpret_cast<const float4*>(src + (size_t)m * ld + kq);
        float* d = As + m * LDA + kq;
        d[0] = tf32r(u.x); d[1] = tf32r(u.y); d[2] = tf32r(u.z); d[3] = tf32r(u.w);
    }
}

// KC with on-the-fly softmax; stats indexed by local k (0..31)
__device__ __forceinline__ void load_KC_sm(float* As, const float* src, int ld,
                                           const float* smax, const float* srin) {
    int tid = threadIdx.x;
#pragma unroll
    for (int i = 0; i < 4; i++) {
        int idx = tid + i * 256;
        int m = idx >> 3;
        int kq = (idx & 7) << 2;
        float4 u = *reinterpret_cast<const float4*>(src + (size_t)m * ld + kq);
        float* d = As + m * LDA + kq;
        d[0] = tf32r(exp_fast(u.x - smax[kq + 0]) * srin[kq + 0]);
        d[1] = tf32r(exp_fast(u.y - smax[kq + 1]) * srin[kq + 1]);
        d[2] = tf32r(exp_fast(u.z - smax[kq + 2]) * srin[kq + 2]);
        d[3] = tf32r(exp_fast(u.w - smax[kq + 3]) * srin[kq + 3]);
    }
}

// MC: operand element (mn, k) at smem[k*LDB + mn]; src row-major [k][mn], ld given
__device__ __forceinline__ void load_MC(float* Bs, const float* src, int ld) {
    int tid = threadIdx.x;
#pragma unroll
    for (int i = 0; i < 4; i++) {
        int idx = tid + i * 256;
        int k = idx >> 5;
        int nq = (idx & 31) << 2;
        float4 u = *reinterpret_cast<const float4*>(src + (size_t)k * ld + nq);
        float* d = Bs + k * LDB + nq;
        d[0] = tf32r(u.x); d[1] = tf32r(u.y); d[2] = tf32r(u.z); d[3] = tf32r(u.w);
    }
}

// MC with on-the-fly softmax; stats indexed by local mn (0..127)
__device__ __forceinline__ void load_MC_sm(float* Bs, const float* src, int ld,
                                           const float* smax, const float* srin) {
    int tid = threadIdx.x;
#pragma unroll
    for (int i = 0; i < 4; i++) {
        int idx = tid + i * 256;
        int k = idx >> 5;
        int nq = (idx & 31) << 2;
        float4 u = *reinterpret_cast<const float4*>(src + (size_t)k * ld + nq);
        float* d = Bs + k * LDB + nq;
        d[0] = tf32r(exp_fast(u.x - smax[nq + 0]) * srin[nq + 0]);
        d[1] = tf32r(exp_fast(u.y - smax[nq + 1]) * srin[nq + 1]);
        d[2] = tf32r(exp_fast(u.z - smax[nq + 2]) * srin[nq + 2]);
        d[3] = tf32r(exp_fast(u.w - smax[nq + 3]) * srin[nq + 3]);
    }
}

// ---------------- warp-tile compute ----------------
// 8 warps in 2x4; warp tile 64x32; acc[4][4][4]
template <bool AMC>
__device__ __forceinline__ void compute_tile(const float* As, const float* Bs,
                                             float (&acc)[4][4][4]) {
    int lane = threadIdx.x & 31;
    int warp = threadIdx.x >> 5;
    int wm = (warp >> 2) * 64;
    int wn = (warp & 3) * 32;
    int g = lane >> 2, t = lane & 3;
#pragma unroll
    for (int kk = 0; kk < 4; kk++) {
        int k0 = kk * 8;
        float a[4][4], b[4][2];
#pragma unroll
        for (int im = 0; im < 4; im++) {
            int m0 = wm + im * 16;
            if (AMC) {
                a[im][0] = As[(k0 + t) * LDB + m0 + g];
                a[im][1] = As[(k0 + t) * LDB + m0 + 8 + g];
                a[im][2] = As[(k0 + t + 4) * LDB + m0 + g];
                a[im][3] = As[(k0 + t + 4) * LDB + m0 + 8 + g];
            } else {
                a[im][0] = As[(m0 + g) * LDA + k0 + t];
                a[im][1] = As[(m0 + 8 + g) * LDA + k0 + t];
                a[im][2] = As[(m0 + g) * LDA + k0 + t + 4];
                a[im][3] = As[(m0 + 8 + g) * LDA + k0 + t + 4];
            }
        }
#pragma unroll
        for (int in = 0; in < 4; in++) {
            int n0 = wn + in * 8;
            b[in][0] = Bs[(k0 + t) * LDB + n0 + g];
            b[in][1] = Bs[(k0 + t + 4) * LDB + n0 + g];
        }
#pragma unroll
        for (int im = 0; im < 4; im++)
#pragma unroll
            for (int in = 0; in < 4; in++)
                mma8(acc[im][in], a[im], b[in]);
    }
}

__device__ __forceinline__ void zero_acc(float (&acc)[4][4][4]) {
#pragma unroll
    for (int i = 0; i < 4; i++)
#pragma unroll
        for (int j = 0; j < 4; j++)
#pragma unroll
            for (int r = 0; r < 4; r++) acc[i][j][r] = 0.f;
}

__device__ __forceinline__ void epilogue(float* C, int ldc, float (&acc)[4][4][4],
                                         const float* bias) {
    int lane = threadIdx.x & 31;
    int warp = threadIdx.x >> 5;
    int wm = (warp >> 2) * 64;
    int wn = (warp & 3) * 32;
    int g = lane >> 2, t = lane & 3;
#pragma unroll
    for (int im = 0; im < 4; im++) {
#pragma unroll
        for (int in = 0; in < 4; in++) {
            int m0 = wm + im * 16;
            int col = wn + in * 8 + t * 2;
            float b0 = 0.f, b1 = 0.f;
            if (bias) { b0 = bias[col]; b1 = bias[col + 1]; }
            float2 w0 = make_float2(acc[im][in][0] + b0, acc[im][in][1] + b1);
            float2 w1 = make_float2(acc[im][in][2] + b0, acc[im][in][3] + b1);
            *reinterpret_cast<float2*>(C + (size_t)(m0 + g) * ldc + col) = w0;
            *reinterpret_cast<float2*>(C + (size_t)(m0 + g + 8) * ldc + col) = w1;
        }
    }
}

// ---------------- K1: QKV projection ----------------
// grid (512, 6): y -> {q,k,v} x {ntile 0,1}
__global__ __launch_bounds__(256, 2)
void k_proj(const float* __restrict__ x,
            const float* __restrict__ Wq, const float* __restrict__ bq,
            const float* __restrict__ Wk, const float* __restrict__ bk,
            const float* __restrict__ Wv, const float* __restrict__ bv) {
    __shared__ float As[BM * LDA];
    __shared__ float Bs[BK * LDB];
    int mt = blockIdx.x;
    int sel = blockIdx.y;
    int which = sel >> 1;
    int nt = sel & 1;
    const float* W    = (which == 0) ? Wq : (which == 1) ? Wk : Wv;
    const float* bias = (which == 0) ? bq : (which == 1) ? bk : bv;
    float* out        = (which == 0) ? g_q : (which == 1) ? g_k : g_v;

    const float* Asrc = x + (size_t)mt * BM * CIN;
    const float* Bsrc = W + nt * BN;

    float acc[4][4][4];
    zero_acc(acc);
    for (int k0 = 0; k0 < CIN; k0 += BK) {
        load_KC(As, Asrc + k0, CIN);
        load_MC(Bs, Bsrc + (size_t)k0 * DIMD, DIMD);
        __syncthreads();
        compute_tile<false>(As, Bs, acc);
        __syncthreads();
    }
    epilogue(out + (size_t)mt * BM * DIMD + nt * BN, DIMD, acc, bias + nt * BN);
}

// ---------------- K2: softmax stats (online max / sum over n) ----------------
// grid 256 = NB * 8 chgroups * 2 tensors; block (32, 8)
__global__ void k_stats() {
    int bid = blockIdx.x;
    int b = bid >> 4;
    int rem = bid & 15;
    int tensor = rem >> 3;
    int cg = rem & 7;
    const float* src = tensor ? g_v : g_k;
    float* omax = tensor ? g_vmax : g_kmax;
    float* orsm = tensor ? g_vrs : g_krs;

    int tx = threadIdx.x, ty = threadIdx.y;
    int ch = cg * 32 + tx;
    const float* p = src + (size_t)b * NPOS * DIMD + ch;

    float m = -1e30f, s = 0.f;
    for (int n = ty; n < NPOS; n += 8) {
        float xv = p[(size_t)n * DIMD];
        if (xv > m) { s = s * exp_fast(m - xv) + 1.f; m = xv; }
        else        { s += exp_fast(xv - m); }
    }
    __shared__ float shm[8][32], shs[8][32];
    shm[ty][tx] = m; shs[ty][tx] = s;
    __syncthreads();
    if (ty == 0) {
        float M = shm[0][tx], S = shs[0][tx];
#pragma unroll
        for (int j = 1; j < 8; j++) {
            float mj = shm[j][tx], sj = shs[j][tx];
            float Mn = fmaxf(M, mj);
            S = S * exp_fast(M - Mn) + sj * exp_fast(mj - Mn);
            M = Mn;
        }
        omax[b * DIMD + ch] = M;
        orsm[b * DIMD + ch] = 1.f / S;
    }
}

// ---------------- K3: gd_part[sp] = sm(k)^T @ q (split-K over n) ----------------
// grid 512 = NB * NSPLIT * 2 * 2
__global__ __launch_bounds__(256, 2)
void k_gd() {
    __shared__ float As[BK * LDB];
    __shared__ float Bs[BK * LDB];
    __shared__ float smax[BM], srin[BM];
    int bid = blockIdx.x;
    int nt = bid & 1;
    int mt = (bid >> 1) & 1;
    int sp = (bid >> 2) & 7;
    int b  = bid >> 5;
    int v0 = mt * BM;
    int d0 = nt * BN;

    if (threadIdx.x < BM) {
        smax[threadIdx.x] = g_kmax[b * DIMD + v0 + threadIdx.x];
        srin[threadIdx.x] = g_krs [b * DIMD + v0 + threadIdx.x];
    }
    __syncthreads();

    const float* Ka = g_k + (size_t)b * NPOS * DIMD + v0;   // [n][v] rows
    const float* Qa = g_q + (size_t)b * NPOS * DIMD + d0;   // [n][d] rows
    int nstart = sp * (NPOS / NSPLIT);

    float acc[4][4][4];
    zero_acc(acc);
    for (int k0 = 0; k0 < NPOS / NSPLIT; k0 += BK) {
        size_t n = (size_t)(nstart + k0);
        load_MC_sm(As, Ka + n * DIMD, DIMD, smax, srin);
        load_MC(Bs, Qa + n * DIMD, DIMD);
        __syncthreads();
        compute_tile<true>(As, Bs, acc);
        __syncthreads();
    }
    epilogue(g_gdp + (((size_t)sp * NB + b) * DIMD + v0) * DIMD + d0, DIMD, acc, nullptr);
}

// ---------------- K3b: reduce split-K partials ----------------
__global__ void k_gdreduce() {
    size_t i = (size_t)blockIdx.x * blockDim.x + threadIdx.x;  // < NB*DIMD*DIMD
    float s = 0.f;
#pragma unroll
    for (int sp = 0; sp < NSPLIT; sp++)
        s += g_gdp[(size_t)sp * NB * DIMD * DIMD + i];
    g_gd[i] = s;
}

// ---------------- K4: M[b] = gd[b] @ Wr ----------------
// grid 128 = NB * 2 * 4
__global__ __launch_bounds__(256, 2)
void k_m(const float* __restrict__ Wr) {
    __shared__ float As[BM * LDA];
    __shared__ float Bs[BK * LDB];
    int bid = blockIdx.x;
    int nt = bid & 3;
    int mt = (bid >> 2) & 1;
    int b  = bid >> 3;

    const float* Asrc = g_gd + ((size_t)b * DIMD + mt * BM) * DIMD;  // [v][d]
    const float* Bsrc = Wr + nt * BN;                                // [d][c]

    float acc[4][4][4];
    zero_acc(acc);
    for (int k0 = 0; k0 < DIMD; k0 += BK) {
        load_KC(As, Asrc + k0, DIMD);
        load_MC(Bs, Bsrc + (size_t)k0 * CIN, CIN);
        __syncthreads();
        compute_tile<false>(As, Bs, acc);
        __syncthreads();
    }
    epilogue(g_Mm + ((size_t)b * DIMD + mt * BM) * CIN + nt * BN, CIN, acc, nullptr);
}

// ---------------- K5: out = sm(v) @ M + br ----------------
// grid 2048 = NB * 32 * 4
__global__ __launch_bounds__(256, 2)
void k_out(const float* __restrict__ br, float* __restrict__ out) {
    __shared__ float As[BM * LDA];
    __shared__ float Bs[BK * LDB];
    __shared__ float smax[DIMD], srin[DIMD];
    int bid = blockIdx.x;
    int nt = bid & 3;
    int mt = (bid >> 2) & 31;
    int b  = bid >> 7;

    if (threadIdx.x < DIMD) {
        smax[threadIdx.x] = g_vmax[b * DIMD + threadIdx.x];
        srin[threadIdx.x] = g_vrs [b * DIMD + threadIdx.x];
    }
    __syncthreads();

    const float* Asrc = g_v + ((size_t)b * NPOS + (size_t)mt * BM) * DIMD;  // [n][vch]
    const float* Bsrc = g_Mm + (size_t)b * DIMD * CIN + nt * BN;            // [v][c]

    float acc[4][4][4];
    zero_acc(acc);
    for (int k0 = 0; k0 < DIMD; k0 += BK) {
        load_KC_sm(As, Asrc + k0, DIMD, smax + k0, srin + k0);
        load_MC(Bs, Bsrc + (size_t)k0 * CIN, CIN);
        __syncthreads();
        compute_tile<false>(As, Bs, acc);
        __syncthreads();
    }
    epilogue(out + ((size_t)b * NPOS + (size_t)mt * BM) * CIN + nt * BN, CIN, acc,
             br + nt * BN);
}

// ---------------- launch ----------------
extern "C" void kernel_launch(void* const* d_in, const int* in_sizes, int n_in,
                              void* d_out, int out_size) {
    (void)in_sizes; (void)n_in; (void)out_size;
    const float* x  = (const float*)d_in[0];
    const float* Wq = (const float*)d_in[1];
    const float* bq = (const float*)d_in[2];
    const float* Wk = (const float*)d_in[3];
    const float* bk = (const float*)d_in[4];
    const float* Wv = (const float*)d_in[5];
    const float* bv = (const float*)d_in[6];
    const float* Wr = (const float*)d_in[7];
    const float* br = (const float*)d_in[8];
    float* out = (float*)d_out;

    k_proj<<<dim3(NTOT / BM, 6), 256>>>(x, Wq, bq, Wk, bk, Wv, bv);
    k_stats<<<NB * 8 * 2, dim3(32, 8)>>>();
    k_gd<<<NB * NSPLIT * 2 * 2, 256>>>();
    k_gdreduce<<<(NB * DIMD * DIMD) / 256, 256>>>();
    k_m<<<NB * 2 * 4, 256>>>(Wr);
    k_out<<<NB * 32 * 4, 256>>>(br, out);
}

// round 2
// speedup vs baseline: 1.0025x; 1.0025x over previous
#include <cuda_runtime.h>
#include <cstdint>

// Problem dims
#define NB    16
#define NPOS  4096
#define CIN   512
#define DIMD  256          // DIM == VDIM == 256
#define NTOT  (NB*NPOS)    // 65536
#define NSPLIT 8

// GEMM tiles
#define BM 128
#define BN 128
#define BK 32
#define LDA 36    // k-contiguous layout row length (BK=32 + 4 pad)
#define LDB 136   // mn-contiguous layout row length (BN=128 + 8 pad)

// ---------------- scratch (device globals; no malloc allowed) ----------------
__device__ float g_q[(size_t)NTOT*DIMD];
__device__ float g_k[(size_t)NTOT*DIMD];
__device__ float g_v[(size_t)NTOT*DIMD];
__device__ float g_kmax[NB*DIMD];
__device__ float g_krs [NB*DIMD];
__device__ float g_vmax[NB*DIMD];
__device__ float g_vrs [NB*DIMD];
__device__ float g_gdp[(size_t)NSPLIT*NB*DIMD*DIMD];
__device__ float g_gd [(size_t)NB*DIMD*DIMD];
__device__ float g_Mm [(size_t)NB*DIMD*CIN];

// ---------------- helpers ----------------
__device__ __forceinline__ float exp_fast(float x) {
    // e^x = 2^(x*log2e); FMA-only (avoid MUFU throughput wall)
    float t = x * 1.4426950408889634f;
    t = fminf(fmaxf(t, -120.f), 120.f);
    float fi = rintf(t);
    float f  = t - fi;                       // [-0.5, 0.5]
    float p = 1.3333558146e-3f;
    p = fmaf(p, f, 9.6181291076e-3f);
    p = fmaf(p, f, 5.5504108665e-2f);
    p = fmaf(p, f, 2.4022650696e-1f);
    p = fmaf(p, f, 6.9314718056e-1f);
    p = fmaf(p, f, 1.0f);
    return __int_as_float(((int)fi + 127) << 23) * p;
}

__device__ __forceinline__ float tf32r(float x) {
    uint32_t u;
    asm("cvt.rna.tf32.f32 %0, %1;" : "=r"(u) : "f"(x));
    return __uint_as_float(u);
}

__device__ __forceinline__ void mma8(float* d, const float* a, const float* b) {
    asm volatile(
        "mma.sync.aligned.m16n8k8.row.col.f32.tf32.tf32.f32 "
        "{%0,%1,%2,%3},{%4,%5,%6,%7},{%8,%9},{%0,%1,%2,%3};\n"
        : "+f"(d[0]), "+f"(d[1]), "+f"(d[2]), "+f"(d[3])
        : "r"(__float_as_uint(a[0])), "r"(__float_as_uint(a[1])),
          "r"(__float_as_uint(a[2])), "r"(__float_as_uint(a[3])),
          "r"(__float_as_uint(b[0])), "r"(__float_as_uint(b[1])));
}

// ---------------- tile loaders ----------------
// KC: operand element (mn, k) at smem[mn*LDA + k]; src row-major [mn][k], ld given
__device__ __forceinline__ void load_KC(float* As, const float* src, int ld) {
    int tid = threadIdx.x;
#pragma unroll
    for (int i = 0; i < 4; i++) {
        int idx = tid + i * 256;
        int m = idx >> 3;
        int kq = (idx & 7) << 2;
        float4 u = *reinterpret_cast<const float4*>(src + (size_t)m * ld + kq);
        float* d = As + m * LDA + kq;
        d[0] = tf32r(u.x); d[1] = tf32r(u.y); d[2] = tf32r(u.z); d[3] = tf32r(u.w);
    }
}

// KC with on-the-fly softmax; stats indexed by local k (0..31)
__device__ __forceinline__ void load_KC_sm(float* As, const float* src, int ld,
                                           const float* smax, const float* srin) {
    int tid = threadIdx.x;
#pragma unroll
    for (int i = 0; i < 4; i++) {
        int idx = tid + i * 256;
        int m = idx >> 3;
        int kq = (idx & 7) << 2;
        float4 u = *reinterpret_cast<const float4*>(src + (size_t)m * ld + kq);
        float* d = As + m * LDA + kq;
        d[0] = tf32r(exp_fast(u.x - smax[kq + 0]) * srin[kq + 0]);
        d[1] = tf32r(exp_fast(u.y - smax[kq + 1]) * srin[kq + 1]);
        d[2] = tf32r(exp_fast(u.z - smax[kq + 2]) * srin[kq + 2]);
        d[3] = tf32r(exp_fast(u.w - smax[kq + 3]) * srin[kq + 3]);
    }
}

// MC: operand element (mn, k) at smem[k*LDB + mn]; src row-major [k][mn], ld given
__device__ __forceinline__ void load_MC(float* Bs, const float* src, int ld) {
    int tid = threadIdx.x;
#pragma unroll
    for (int i = 0; i < 4; i++) {
        int idx = tid + i * 256;
        int k = idx >> 5;
        int nq = (idx & 31) << 2;
        float4 u = *reinterpret_cast<const float4*>(src + (size_t)k * ld + nq);
        float* d = Bs + k * LDB + nq;
        d[0] = tf32r(u.x); d[1] = tf32r(u.y); d[2] = tf32r(u.z); d[3] = tf32r(u.w);
    }
}

// MC with on-the-fly softmax; stats indexed by local mn (0..127)
__device__ __forceinline__ void load_MC_sm(float* Bs, const float* src, int ld,
                                           const float* smax, const float* srin) {
    int tid = threadIdx.x;
#pragma unroll
    for (int i = 0; i < 4; i++) {
        int idx = tid + i * 256;
        int k = idx >> 5;
        int nq = (idx & 31) << 2;
        float4 u = *reinterpret_cast<const float4*>(src + (size_t)k * ld + nq);
        float* d = Bs + k * LDB + nq;
        d[0] = tf32r(exp_fast(u.x - smax[nq + 0]) * srin[nq + 0]);
        d[1] = tf32r(exp_fast(u.y - smax[nq + 1]) * srin[nq + 1]);
        d[2] = tf32r(exp_fast(u.z - smax[nq + 2]) * srin[nq + 2]);
        d[3] = tf32r(exp_fast(u.w - smax[nq + 3]) * srin[nq + 3]);
    }
}

// ---------------- warp-tile compute ----------------
// 8 warps in 2x4; warp tile 64x32; acc[4][4][4]
template <bool AMC>
__device__ __forceinline__ void compute_tile(const float* As, const float* Bs,
                                             float (&acc)[4][4][4]) {
    int lane = threadIdx.x & 31;
    int warp = threadIdx.x >> 5;
    int wm = (warp >> 2) * 64;
    int wn = (warp & 3) * 32;
    int g = lane >> 2, t = lane & 3;
#pragma unroll
    for (int kk = 0; kk < 4; kk++) {
        int k0 = kk * 8;
        float a[4][4], b[4][2];
#pragma unroll
        for (int im = 0; im < 4; im++) {
            int m0 = wm + im * 16;
            if (AMC) {
                a[im][0] = As[(k0 + t) * LDB + m0 + g];
                a[im][1] = As[(k0 + t) * LDB + m0 + 8 + g];
                a[im][2] = As[(k0 + t + 4) * LDB + m0 + g];
                a[im][3] = As[(k0 + t + 4) * LDB + m0 + 8 + g];
            } else {
                a[im][0] = As[(m0 + g) * LDA + k0 + t];
                a[im][1] = As[(m0 + 8 + g) * LDA + k0 + t];
                a[im][2] = As[(m0 + g) * LDA + k0 + t + 4];
                a[im][3] = As[(m0 + 8 + g) * LDA + k0 + t + 4];
            }
        }
#pragma unroll
        for (int in = 0; in < 4; in++) {
            int n0 = wn + in * 8;
            b[in][0] = Bs[(k0 + t) * LDB + n0 + g];
            b[in][1] = Bs[(k0 + t + 4) * LDB + n0 + g];
        }
#pragma unroll
        for (int im = 0; im < 4; im++)
#pragma unroll
            for (int in = 0; in < 4; in++)
                mma8(acc[im][in], a[im], b[in]);
    }
}

__device__ __forceinline__ void zero_acc(float (&acc)[4][4][4]) {
#pragma unroll
    for (int i = 0; i < 4; i++)
#pragma unroll
        for (int j = 0; j < 4; j++)
#pragma unroll
            for (int r = 0; r < 4; r++) acc[i][j][r] = 0.f;
}

__device__ __forceinline__ void epilogue(float* C, int ldc, float (&acc)[4][4][4],
                                         const float* bias) {
    int lane = threadIdx.x & 31;
    int warp = threadIdx.x >> 5;
    int wm = (warp >> 2) * 64;
    int wn = (warp & 3) * 32;
    int g = lane >> 2, t = lane & 3;
#pragma unroll
    for (int im = 0; im < 4; im++) {
#pragma unroll
        for (int in = 0; in < 4; in++) {
            int m0 = wm + im * 16;
            int col = wn + in * 8 + t * 2;
            float b0 = 0.f, b1 = 0.f;
            if (bias) { b0 = bias[col]; b1 = bias[col + 1]; }
            float2 w0 = make_float2(acc[im][in][0] + b0, acc[im][in][1] + b1);
            float2 w1 = make_float2(acc[im][in][2] + b0, acc[im][in][3] + b1);
            *reinterpret_cast<float2*>(C + (size_t)(m0 + g) * ldc + col) = w0;
            *reinterpret_cast<float2*>(C + (size_t)(m0 + g + 8) * ldc + col) = w1;
        }
    }
}

// ---------------- K1: QKV projection ----------------
// grid (512, 6): y -> {q,k,v} x {ntile 0,1}
__global__ __launch_bounds__(256, 2)
void k_proj(const float* __restrict__ x,
            const float* __restrict__ Wq, const float* __restrict__ bq,
            const float* __restrict__ Wk, const float* __restrict__ bk,
            const float* __restrict__ Wv, const float* __restrict__ bv) {
    __shared__ float As[BM * LDA];
    __shared__ float Bs[BK * LDB];
    int mt = blockIdx.x;
    int sel = blockIdx.y;
    int which = sel >> 1;
    int nt = sel & 1;
    const float* W    = (which == 0) ? Wq : (which == 1) ? Wk : Wv;
    const float* bias = (which == 0) ? bq : (which == 1) ? bk : bv;
    float* out        = (which == 0) ? g_q : (which == 1) ? g_k : g_v;

    const float* Asrc = x + (size_t)mt * BM * CIN;
    const float* Bsrc = W + nt * BN;

    float acc[4][4][4];
    zero_acc(acc);
    for (int k0 = 0; k0 < CIN; k0 += BK) {
        load_KC(As, Asrc + k0, CIN);
        load_MC(Bs, Bsrc + (size_t)k0 * DIMD, DIMD);
        __syncthreads();
        compute_tile<false>(As, Bs, acc);
        __syncthreads();
    }
    epilogue(out + (size_t)mt * BM * DIMD + nt * BN, DIMD, acc, bias + nt * BN);
}

// ---------------- K2: softmax stats (online max / sum over n) ----------------
// grid 256 = NB * 8 chgroups * 2 tensors; block (32, 8)
__global__ void k_stats() {
    int bid = blockIdx.x;
    int b = bid >> 4;
    int rem = bid & 15;
    int tensor = rem >> 3;
    int cg = rem & 7;
    const float* src = tensor ? g_v : g_k;
    float* omax = tensor ? g_vmax : g_kmax;
    float* orsm = tensor ? g_vrs : g_krs;

    int tx = threadIdx.x, ty = threadIdx.y;
    int ch = cg * 32 + tx;
    const float* p = src + (size_t)b * NPOS * DIMD + ch;

    float m = -1e30f, s = 0.f;
    for (int n = ty; n < NPOS; n += 8) {
        float xv = p[(size_t)n * DIMD];
        if (xv > m) { s = s * exp_fast(m - xv) + 1.f; m = xv; }
        else        { s += exp_fast(xv - m); }
    }
    __shared__ float shm[8][32], shs[8][32];
    shm[ty][tx] = m; shs[ty][tx] = s;
    __syncthreads();
    if (ty == 0) {
        float M = shm[0][tx], S = shs[0][tx];
#pragma unroll
        for (int j = 1; j < 8; j++) {
            float mj = shm[j][tx], sj = shs[j][tx];
            float Mn = fmaxf(M, mj);
            S = S * exp_fast(M - Mn) + sj * exp_fast(mj - Mn);
            M = Mn;
        }
        omax[b * DIMD + ch] = M;
        orsm[b * DIMD + ch] = 1.f / S;
    }
}

// ---------------- K3: gd_part[sp] = sm(k)^T @ q (split-K over n) ----------------
// grid 512 = NB * NSPLIT * 2 * 2
__global__ __launch_bounds__(256, 2)
void k_gd() {
    __shared__ float As[BK * LDB];
    __shared__ float Bs[BK * LDB];
    __shared__ float smax[BM], srin[BM];
    int bid = blockIdx.x;
    int nt = bid & 1;
    int mt = (bid >> 1) & 1;
    int sp = (bid >> 2) & 7;
    int b  = bid >> 5;
    int v0 = mt * BM;
    int d0 = nt * BN;

    if (threadIdx.x < BM) {
        smax[threadIdx.x] = g_kmax[b * DIMD + v0 + threadIdx.x];
        srin[threadIdx.x] = g_krs [b * DIMD + v0 + threadIdx.x];
    }
    __syncthreads();

    const float* Ka = g_k + (size_t)b * NPOS * DIMD + v0;   // [n][v] rows
    const float* Qa = g_q + (size_t)b * NPOS * DIMD + d0;   // [n][d] rows
    int nstart = sp * (NPOS / NSPLIT);

    float acc[4][4][4];
    zero_acc(acc);
    for (int k0 = 0; k0 < NPOS / NSPLIT; k0 += BK) {
        size_t n = (size_t)(nstart + k0);
        load_MC_sm(As, Ka + n * DIMD, DIMD, smax, srin);
        load_MC(Bs, Qa + n * DIMD, DIMD);
        __syncthreads();
        compute_tile<true>(As, Bs, acc);
        __syncthreads();
    }
    epilogue(g_gdp + (((size_t)sp * NB + b) * DIMD + v0) * DIMD + d0, DIMD, acc, nullptr);
}

// ---------------- K3b: reduce split-K partials ----------------
__global__ void k_gdreduce() {
    size_t i = (size_t)blockIdx.x * blockDim.x + threadIdx.x;  // < NB*DIMD*DIMD
    float s = 0.f;
#pragma unroll
    for (int sp = 0; sp < NSPLIT; sp++)
        s += g_gdp[(size_t)sp * NB * DIMD * DIMD + i];
    g_gd[i] = s;
}

// ---------------- K4: M[b] = gd[b] @ Wr ----------------
// grid 128 = NB * 2 * 4
__global__ __launch_bounds__(256, 2)
void k_m(const float* __restrict__ Wr) {
    __shared__ float As[BM * LDA];
    __shared__ float Bs[BK * LDB];
    int bid = blockIdx.x;
    int nt = bid & 3;
    int mt = (bid >> 2) & 1;
    int b  = bid >> 3;

    const float* Asrc = g_gd + ((size_t)b * DIMD + mt * BM) * DIMD;  // [v][d]
    const float* Bsrc = Wr + nt * BN;                                // [d][c]

    float acc[4][4][4];
    zero_acc(acc);
    for (int k0 = 0; k0 < DIMD; k0 += BK) {
        load_KC(As, Asrc + k0, DIMD);
        load_MC(Bs, Bsrc + (size_t)k0 * CIN, CIN);
        __syncthreads();
        compute_tile<false>(As, Bs, acc);
        __syncthreads();
    }
    epilogue(g_Mm + ((size_t)b * DIMD + mt * BM) * CIN + nt * BN, CIN, acc, nullptr);
}

// ---------------- K5: out = sm(v) @ M + br ----------------
// grid 2048 = NB * 32 * 4
__global__ __launch_bounds__(256, 2)
void k_out(const float* __restrict__ br, float* __restrict__ out) {
    __shared__ float As[BM * LDA];
    __shared__ float Bs[BK * LDB];
    __shared__ float smax[DIMD], srin[DIMD];
    int bid = blockIdx.x;
    int nt = bid & 3;
    int mt = (bid >> 2) & 31;
    int b  = bid >> 7;

    if (threadIdx.x < DIMD) {
        smax[threadIdx.x] = g_vmax[b * DIMD + threadIdx.x];
        srin[threadIdx.x] = g_vrs [b * DIMD + threadIdx.x];
    }
    __syncthreads();

    const float* Asrc = g_v + ((size_t)b * NPOS + (size_t)mt * BM) * DIMD;  // [n][vch]
    const float* Bsrc = g_Mm + (size_t)b * DIMD * CIN + nt * BN;            // [v][c]

    float acc[4][4][4];
    zero_acc(acc);
    for (int k0 = 0; k0 < DIMD; k0 += BK) {
        load_KC_sm(As, Asrc + k0, DIMD, smax + k0, srin + k0);
        load_MC(Bs, Bsrc + (size_t)k0 * CIN, CIN);
        __syncthreads();
        compute_tile<false>(As, Bs, acc);
        __syncthreads();
    }
    epilogue(out + ((size_t)b * NPOS + (size_t)mt * BM) * CIN + nt * BN, CIN, acc,
             br + nt * BN);
}

// ---------------- launch ----------------
extern "C" void kernel_launch(void* const* d_in, const int* in_sizes, int n_in,
                              void* d_out, int out_size) {
    (void)in_sizes; (void)n_in; (void)out_size;
    const float* x  = (const float*)d_in[0];
    const float* Wq = (const float*)d_in[1];
    const float* bq = (const float*)d_in[2];
    const float* Wk = (const float*)d_in[3];
    const float* bk = (const float*)d_in[4];
    const float* Wv = (const float*)d_in[5];
    const float* bv = (const float*)d_in[6];
    const float* Wr = (const float*)d_in[7];
    const float* br = (const float*)d_in[8];
    float* out = (float*)d_out;

    k_proj<<<dim3(NTOT / BM, 6), 256>>>(x, Wq, bq, Wk, bk, Wv, bv);
    k_stats<<<NB * 8 * 2, dim3(32, 8)>>>();
    k_gd<<<NB * NSPLIT * 2 * 2, 256>>>();
    k_gdreduce<<<(NB * DIMD * DIMD) / 256, 256>>>();
    k_m<<<NB * 2 * 4, 256>>>(Wr);
    k_out<<<NB * 32 * 4, 256>>>(br, out);
}

// round 5
// speedup vs baseline: 1.3669x; 1.3635x over previous
#include <cuda_runtime.h>
#include <cuda_fp16.h>
#include <cstdint>

#define NB    16
#define NPOS  4096
#define CIN   512
#define DIMD  256
#define NTOT  (NB*NPOS)
#define NSPLIT 8

#define BM 128
#define BN 128
#define BK 32
#define LDAH 40    // K-major smem row: 32 halves + 8 pad (80B stride -> conflict-free ldmatrix)
#define LDBH 136   // MN-major smem row: 128 halves + 8 pad (272B stride -> conflict-free)

// ---------------- scratch ----------------
__device__ float g_q[(size_t)NTOT*DIMD];
__device__ float g_k[(size_t)NTOT*DIMD];
__device__ float g_v[(size_t)NTOT*DIMD];
__device__ float g_kmax[NB*DIMD];
__device__ float g_krs [NB*DIMD];
__device__ float g_vmax[NB*DIMD];
__device__ float g_vrs [NB*DIMD];
__device__ float g_gdp[(size_t)NSPLIT*NB*DIMD*DIMD];
__device__ float g_gd [(size_t)NB*DIMD*DIMD];
__device__ __half g_Wth [(size_t)3*DIMD*CIN];  // [which][n=256][k=512]
__device__ __half g_Wrth[(size_t)CIN*DIMD];    // [c=512][d=256]
__device__ float  g_Mt  [(size_t)NB*CIN*DIMD]; // [b][c=512][v=256]

// ---------------- helpers ----------------
__device__ __forceinline__ float exp_fast(float x) {
    float t = x * 1.4426950408889634f;
    t = fminf(fmaxf(t, -120.f), 120.f);
    float fi = rintf(t);
    float f  = t - fi;
    float p = 1.3333558146e-3f;
    p = fmaf(p, f, 9.6181291076e-3f);
    p = fmaf(p, f, 5.5504108665e-2f);
    p = fmaf(p, f, 2.4022650696e-1f);
    p = fmaf(p, f, 6.9314718056e-1f);
    p = fmaf(p, f, 1.0f);
    return __int_as_float(((int)fi + 127) << 23) * p;
}
__device__ __forceinline__ uint32_t smem_u32(const void* p) {
    uint32_t a;
    asm("{ .reg .u64 t; cvta.to.shared.u64 t, %1; cvt.u32.u64 %0, t; }" : "=r"(a) : "l"(p));
    return a;
}
__device__ __forceinline__ uint32_t f22h(float a, float b) {
    __half2 h = __floats2half2_rn(a, b);
    return *reinterpret_cast<uint32_t*>(&h);
}
__device__ __forceinline__ void ldsm4(uint32_t (&r)[4], uint32_t addr) {
    asm volatile("ldmatrix.sync.aligned.m8n8.x4.shared.b16 {%0,%1,%2,%3}, [%4];"
        : "=r"(r[0]), "=r"(r[1]), "=r"(r[2]), "=r"(r[3]) : "r"(addr));
}
__device__ __forceinline__ void ldsm4t(uint32_t (&r)[4], uint32_t addr) {
    asm volatile("ldmatrix.sync.aligned.m8n8.x4.trans.shared.b16 {%0,%1,%2,%3}, [%4];"
        : "=r"(r[0]), "=r"(r[1]), "=r"(r[2]), "=r"(r[3]) : "r"(addr));
}
__device__ __forceinline__ void mma16816(float* d, const uint32_t* a, const uint32_t* b) {
    asm volatile(
        "mma.sync.aligned.m16n8k16.row.col.f32.f16.f16.f32 "
        "{%0,%1,%2,%3},{%4,%5,%6,%7},{%8,%9},{%0,%1,%2,%3};"
        : "+f"(d[0]), "+f"(d[1]), "+f"(d[2]), "+f"(d[3])
        : "r"(a[0]), "r"(a[1]), "r"(a[2]), "r"(a[3]), "r"(b[0]), "r"(b[1]));
}

// ---------------- K-major tile loaders (dst [128 rows][LDAH] half) ----------------
__device__ __forceinline__ void pf_KC(const float* __restrict__ src, int ld, float4 (&ra)[4]) {
    const int tid = threadIdx.x;
#pragma unroll
    for (int i = 0; i < 4; i++) {
        int idx = tid + i*256, m = idx >> 3, kq = (idx & 7) << 2;
        ra[i] = *(const float4*)(src + (size_t)m*ld + kq);
    }
}
__device__ __forceinline__ void st_KC(__half* As, const float4 (&ra)[4]) {
    const int tid = threadIdx.x;
#pragma unroll
    for (int i = 0; i < 4; i++) {
        int idx = tid + i*256, m = idx >> 3, kq = (idx & 7) << 2;
        *(uint2*)(As + m*LDAH + kq) = make_uint2(f22h(ra[i].x, ra[i].y), f22h(ra[i].z, ra[i].w));
    }
}
__device__ __forceinline__ void st_KC_sm(__half* As, const float4 (&ra)[4],
                                         const float* smax, const float* srin) {
    const int tid = threadIdx.x;
#pragma unroll
    for (int i = 0; i < 4; i++) {
        int idx = tid + i*256, m = idx >> 3, kq = (idx & 7) << 2;
        float a = exp_fast(ra[i].x - smax[kq+0]) * srin[kq+0];
        float b = exp_fast(ra[i].y - smax[kq+1]) * srin[kq+1];
        float c = exp_fast(ra[i].z - smax[kq+2]) * srin[kq+2];
        float d = exp_fast(ra[i].w - smax[kq+3]) * srin[kq+3];
        *(uint2*)(As + m*LDAH + kq) = make_uint2(f22h(a, b), f22h(c, d));
    }
}
__device__ __forceinline__ void ld_B_f32(__half* Bs, const float* __restrict__ src, int ld) {
    const int tid = threadIdx.x;
#pragma unroll
    for (int i = 0; i < 4; i++) {
        int idx = tid + i*256, n = idx >> 3, kq = (idx & 7) << 2;
        float4 u = *(const float4*)(src + (size_t)n*ld + kq);
        *(uint2*)(Bs + n*LDAH + kq) = make_uint2(f22h(u.x, u.y), f22h(u.z, u.w));
    }
}
// FIXED: uint4 (8 halves) per thread -> full 128x32 coverage (was uint2, half tile uninit)
__device__ __forceinline__ void ld_B_h16(__half* Bs, const __half* __restrict__ src, int ld) {
    const int tid = threadIdx.x;
#pragma unroll
    for (int i = 0; i < 2; i++) {
        int idx = tid + i*256, n = idx >> 2, kq = (idx & 3) << 3;
        *(uint4*)(Bs + n*LDAH + kq) = *(const uint4*)(src + (size_t)n*ld + kq);
    }
}

// ---------------- MN-major tile loaders (dst [32 k-rows][LDBH] half) ----------------
__device__ __forceinline__ void pf_T(const float* __restrict__ src, int ld, float4 (&ra)[4]) {
    const int tid = threadIdx.x;
#pragma unroll
    for (int i = 0; i < 4; i++) {
        int idx = tid + i*256, k = idx >> 5, nq = (idx & 31) << 2;
        ra[i] = *(const float4*)(src + (size_t)k*ld + nq);
    }
}
__device__ __forceinline__ void st_T_sm(__half* Ts, const float4 (&ra)[4],
                                        const float* smax, const float* srin) {
    const int tid = threadIdx.x;
#pragma unroll
    for (int i = 0; i < 4; i++) {
        int idx = tid + i*256, k = idx >> 5, nq = (idx & 31) << 2;
        float a = exp_fast(ra[i].x - smax[nq+0]) * srin[nq+0];
        float b = exp_fast(ra[i].y - smax[nq+1]) * srin[nq+1];
        float c = exp_fast(ra[i].z - smax[nq+2]) * srin[nq+2];
        float d = exp_fast(ra[i].w - smax[nq+3]) * srin[nq+3];
        *(uint2*)(Ts + k*LDBH + nq) = make_uint2(f22h(a, b), f22h(c, d));
    }
}
__device__ __forceinline__ void ld_T_f32(__half* Ts, const float* __restrict__ src, int ld) {
    const int tid = threadIdx.x;
#pragma unroll
    for (int i = 0; i < 4; i++) {
        int idx = tid + i*256, k = idx >> 5, nq = (idx & 31) << 2;
        float4 u = *(const float4*)(src + (size_t)k*ld + nq);
        *(uint2*)(Ts + k*LDBH + nq) = make_uint2(f22h(u.x, u.y), f22h(u.z, u.w));
    }
}

// ---------------- warp compute: 8 warps 2x4, warp tile 64x32 ----------------
__device__ __forceinline__ void compute_f16(uint32_t Ab, uint32_t Bb, float (&acc)[4][4][4]) {
    const int lane = threadIdx.x & 31, warp = threadIdx.x >> 5;
    const int wm = (warp >> 2) * 64, wn = (warp & 3) * 32;
#pragma unroll
    for (int kk = 0; kk < 2; kk++) {
        int k0 = kk * 16;
        uint32_t a[4][4], b[4][2];
#pragma unroll
        for (int im = 0; im < 4; im++) {
            int m0 = wm + im * 16;
            uint32_t addr = Ab + (((m0 + ((lane>>3)&1)*8 + (lane&7)) * LDAH
                                  + k0 + (lane>>4)*8) << 1);
            ldsm4(a[im], addr);
        }
#pragma unroll
        for (int p = 0; p < 2; p++) {
            int n0 = wn + p * 16;
            uint32_t r[4];
            uint32_t addr = Bb + (((n0 + ((lane>>4)&1)*8 + (lane&7)) * LDAH
                                  + k0 + ((lane>>3)&1)*8) << 1);
            ldsm4(r, addr);
            b[2*p][0] = r[0]; b[2*p][1] = r[1];
            b[2*p+1][0] = r[2]; b[2*p+1][1] = r[3];
        }
#pragma unroll
        for (int im = 0; im < 4; im++)
#pragma unroll
            for (int in = 0; in < 4; in++)
                mma16816(acc[im][in], a[im], b[in]);
    }
}
__device__ __forceinline__ void compute_f16_T(uint32_t Ab, uint32_t Bb, float (&acc)[4][4][4]) {
    const int lane = threadIdx.x & 31, warp = threadIdx.x >> 5;
    const int wm = (warp >> 2) * 64, wn = (warp & 3) * 32;
#pragma unroll
    for (int kk = 0; kk < 2; kk++) {
        int k0 = kk * 16;
        uint32_t a[4][4], b[4][2];
#pragma unroll
        for (int im = 0; im < 4; im++) {
            int m0 = wm + im * 16;
            uint32_t addr = Ab + (((k0 + ((lane>>4)&1)*8 + (lane&7)) * LDBH
                                  + m0 + ((lane>>3)&1)*8) << 1);
            ldsm4t(a[im], addr);
        }
#pragma unroll
        for (int p = 0; p < 2; p++) {
            int n0 = wn + p * 16;
            uint32_t r[4];
            uint32_t addr = Bb + (((k0 + ((lane>>3)&1)*8 + (lane&7)) * LDBH
                                  + n0 + ((lane>>4)&1)*8) << 1);
            ldsm4t(r, addr);
            b[2*p][0] = r[0]; b[2*p][1] = r[1];
            b[2*p+1][0] = r[2]; b[2*p+1][1] = r[3];
        }
#pragma unroll
        for (int im = 0; im < 4; im++)
#pragma unroll
            for (int in = 0; in < 4; in++)
                mma16816(acc[im][in], a[im], b[in]);
    }
}
__device__ __forceinline__ void zero_acc(float (&acc)[4][4][4]) {
#pragma unroll
    for (int i = 0; i < 4; i++)
#pragma unroll
        for (int j = 0; j < 4; j++)
#pragma unroll
            for (int r = 0; r < 4; r++) acc[i][j][r] = 0.f;
}
__device__ __forceinline__ void epilogue(float* C, int ldc, float (&acc)[4][4][4],
                                         const float* bias) {
    const int lane = threadIdx.x & 31, warp = threadIdx.x >> 5;
    const int wm = (warp >> 2) * 64, wn = (warp & 3) * 32;
    const int g = lane >> 2, t = lane & 3;
#pragma unroll
    for (int im = 0; im < 4; im++)
#pragma unroll
        for (int in = 0; in < 4; in++) {
            int m0 = wm + im * 16;
            int col = wn + in * 8 + t * 2;
            float b0 = 0.f, b1 = 0.f;
            if (bias) { b0 = bias[col]; b1 = bias[col + 1]; }
            *(float2*)(C + (size_t)(m0 + g) * ldc + col) =
                make_float2(acc[im][in][0] + b0, acc[im][in][1] + b1);
            *(float2*)(C + (size_t)(m0 + g + 8) * ldc + col) =
                make_float2(acc[im][in][2] + b0, acc[im][in][3] + b1);
        }
}

// ---------------- K1: QKV projection ----------------
__global__ __launch_bounds__(256, 2)
void k_proj(const float* __restrict__ x, const float* __restrict__ bq,
            const float* __restrict__ bk, const float* __restrict__ bv) {
    __shared__ __half As[BM * LDAH];
    __shared__ __half Bs[BM * LDAH];
    int mt = blockIdx.x, sel = blockIdx.y;
    int which = sel >> 1, nt = sel & 1;
    const float* bias = (which == 0) ? bq : (which == 1) ? bk : bv;
    float* out        = (which == 0) ? g_q : (which == 1) ? g_k : g_v;
    const float* Asrc  = x + (size_t)mt * BM * CIN;
    const __half* Bsrc = g_Wth + ((size_t)which * DIMD + nt * BN) * CIN;

    float acc[4][4][4];
    zero_acc(acc);
    float4 ra[4];
    pf_KC(Asrc, CIN, ra);
    for (int k0 = 0; k0 < CIN; k0 += BK) {
        st_KC(As, ra);
        ld_B_h16(Bs, Bsrc + k0, CIN);
        __syncthreads();
        if (k0 + BK < CIN) pf_KC(Asrc + k0 + BK, CIN, ra);
        compute_f16(smem_u32(As), smem_u32(Bs), acc);
        __syncthreads();
    }
    epilogue(out + (size_t)mt * BM * DIMD + nt * BN, DIMD, acc, bias + nt * BN);
}

// ---------------- K2: softmax stats ----------------
__global__ void k_stats() {
    int bid = blockIdx.x;
    int b = bid >> 4, rem = bid & 15;
    int tensor = rem >> 3, cg = rem & 7;
    const float* src = tensor ? g_v : g_k;
    float* omax = tensor ? g_vmax : g_kmax;
    float* orsm = tensor ? g_vrs : g_krs;
    int tx = threadIdx.x, ty = threadIdx.y;
    int ch = cg * 32 + tx;
    const float* p = src + (size_t)b * NPOS * DIMD + ch;
    float m = -1e30f, s = 0.f;
    for (int n = ty; n < NPOS; n += 8) {
        float xv = p[(size_t)n * DIMD];
        if (xv > m) { s = s * exp_fast(m - xv) + 1.f; m = xv; }
        else        { s += exp_fast(xv - m); }
    }
    __shared__ float shm[8][32], shs[8][32];
    shm[ty][tx] = m; shs[ty][tx] = s;
    __syncthreads();
    if (ty == 0) {
        float M = shm[0][tx], S = shs[0][tx];
#pragma unroll
        for (int j = 1; j < 8; j++) {
            float mj = shm[j][tx], sj = shs[j][tx];
            float Mn = fmaxf(M, mj);
            S = S * exp_fast(M - Mn) + sj * exp_fast(mj - Mn);
            M = Mn;
        }
        omax[b * DIMD + ch] = M;
        orsm[b * DIMD + ch] = 1.f / S;
    }
}

// ---------------- K3: gd partials (trans path) ----------------
__global__ __launch_bounds__(256, 2)
void k_gd() {
    __shared__ __half As[BK * LDBH];
    __shared__ __half Bs[BK * LDBH];
    __shared__ float smax[BM], srin[BM];
    int bid = blockIdx.x;
    int nt = bid & 1, mt = (bid >> 1) & 1, sp = (bid >> 2) & 7, b = bid >> 5;
    int v0 = mt * BM, d0 = nt * BN;
    if (threadIdx.x < BM) {
        smax[threadIdx.x] = g_kmax[b * DIMD + v0 + threadIdx.x];
        srin[threadIdx.x] = g_krs [b * DIMD + v0 + threadIdx.x];
    }
    __syncthreads();
    const float* Ka = g_k + (size_t)b * NPOS * DIMD + v0;
    const float* Qa = g_q + (size_t)b * NPOS * DIMD + d0;
    int nstart = sp * (NPOS / NSPLIT);

    float acc[4][4][4];
    zero_acc(acc);
    float4 ra[4];
    pf_T(Ka + (size_t)nstart * DIMD, DIMD, ra);
    for (int k0 = 0; k0 < NPOS / NSPLIT; k0 += BK) {
        size_t n = (size_t)(nstart + k0);
        st_T_sm(As, ra, smax, srin);
        ld_T_f32(Bs, Qa + n * DIMD, DIMD);
        __syncthreads();
        if (k0 + BK < NPOS / NSPLIT)
            pf_T(Ka + (n + BK) * DIMD, DIMD, ra);
        compute_f16_T(smem_u32(As), smem_u32(Bs), acc);
        __syncthreads();
    }
    epilogue(g_gdp + (((size_t)sp * NB + b) * DIMD + v0) * DIMD + d0, DIMD, acc, nullptr);
}
__global__ void k_gdreduce() {
    size_t i = (size_t)blockIdx.x * blockDim.x + threadIdx.x;
    float s = 0.f;
#pragma unroll
    for (int sp = 0; sp < NSPLIT; sp++)
        s += g_gdp[(size_t)sp * NB * DIMD * DIMD + i];
    g_gd[i] = s;
}

// ---------------- K4: Mt[b] = Wr^T @ gd^T  (Mt[c][v]) ----------------
__global__ __launch_bounds__(256, 2)
void k_m() {
    __shared__ __half As[BM * LDAH];
    __shared__ __half Bs[BM * LDAH];
    int mt = blockIdx.x >> 1, nt = blockIdx.x & 1, b = blockIdx.y;
    const __half* Asrc = g_Wrth + (size_t)mt * BM * DIMD;                 // [c][d]
    const float*  Bsrc = g_gd + ((size_t)b * DIMD + nt * BN) * DIMD;     // [v][d]
    float acc[4][4][4];
    zero_acc(acc);
    for (int k0 = 0; k0 < DIMD; k0 += BK) {
        ld_B_h16(As, Asrc + k0, DIMD);
        ld_B_f32(Bs, Bsrc + k0, DIMD);
        __syncthreads();
        compute_f16(smem_u32(As), smem_u32(Bs), acc);
        __syncthreads();
    }
    epilogue(g_Mt + ((size_t)b * CIN + mt * BM) * DIMD + nt * BN, DIMD, acc, nullptr);
}

// ---------------- K5: out = sm(v) @ Mt^T + br ----------------
__global__ __launch_bounds__(256, 2)
void k_out(const float* __restrict__ br, float* __restrict__ out) {
    __shared__ __half As[BM * LDAH];
    __shared__ __half Bs[BM * LDAH];
    __shared__ float smax[DIMD], srin[DIMD];
    int mt = blockIdx.x, nt = blockIdx.y;
    int b = mt >> 5;
    if (threadIdx.x < DIMD) {
        smax[threadIdx.x] = g_vmax[b * DIMD + threadIdx.x];
        srin[threadIdx.x] = g_vrs [b * DIMD + threadIdx.x];
    }
    __syncthreads();
    const float* Asrc = g_v + (size_t)mt * BM * DIMD;                    // [n][vch]
    const float* Bsrc = g_Mt + ((size_t)b * CIN + nt * BN) * DIMD;       // [c][v]

    float acc[4][4][4];
    zero_acc(acc);
    float4 ra[4];
    pf_KC(Asrc, DIMD, ra);
    for (int k0 = 0; k0 < DIMD; k0 += BK) {
        st_KC_sm(As, ra, smax + k0, srin + k0);
        ld_B_f32(Bs, Bsrc + k0, DIMD);
        __syncthreads();
        if (k0 + BK < DIMD) pf_KC(Asrc + k0 + BK, DIMD, ra);
        compute_f16(smem_u32(As), smem_u32(Bs), acc);
        __syncthreads();
    }
    epilogue(out + (size_t)mt * BM * CIN + nt * BN, CIN, acc, br + nt * BN);
}

// ---------------- weight transpose + fp16 convert ----------------
__global__ void k_trh(const float* __restrict__ src, __half* __restrict__ dst, int R, int C) {
    __shared__ float t[32][33];
    int bx = blockIdx.x * 32, by = blockIdx.y * 32;
    for (int j = threadIdx.y; j < 32; j += 8)
        t[j][threadIdx.x] = src[(size_t)(by + j) * C + bx + threadIdx.x];
    __syncthreads();
    for (int j = threadIdx.y; j < 32; j += 8)
        dst[(size_t)(bx + j) * R + by + threadIdx.x] = __float2half_rn(t[threadIdx.x][j]);
}

// ---------------- launch ----------------
extern "C" void kernel_launch(void* const* d_in, const int* in_sizes, int n_in,
                              void* d_out, int out_size) {
    (void)in_sizes; (void)n_in; (void)out_size;
    const float* x  = (const float*)d_in[0];
    const float* Wq = (const float*)d_in[1];
    const float* bq = (const float*)d_in[2];
    const float* Wk = (const float*)d_in[3];
    const float* bk = (const float*)d_in[4];
    const float* Wv = (const float*)d_in[5];
    const float* bv = (const float*)d_in[6];
    const float* Wr = (const float*)d_in[7];
    const float* br = (const float*)d_in[8];
    float* out = (float*)d_out;

    __half* wt = nullptr; __half* wrt = nullptr;
    cudaGetSymbolAddress((void**)&wt, g_Wth);
    cudaGetSymbolAddress((void**)&wrt, g_Wrth);

    k_trh<<<dim3(8, 16), dim3(32, 8)>>>(Wq, wt, CIN, DIMD);
    k_trh<<<dim3(8, 16), dim3(32, 8)>>>(Wk, wt + (size_t)DIMD * CIN, CIN, DIMD);
    k_trh<<<dim3(8, 16), dim3(32, 8)>>>(Wv, wt + (size_t)2 * DIMD * CIN, CIN, DIMD);
    k_trh<<<dim3(16, 8), dim3(32, 8)>>>(Wr, wrt, DIMD, CIN);

    k_proj<<<dim3(NTOT / BM, 6), 256>>>(x, bq, bk, bv);
    k_stats<<<NB * 8 * 2, dim3(32, 8)>>>();
    k_gd<<<NB * NSPLIT * 2 * 2, 256>>>();
    k_gdreduce<<<(NB * DIMD * DIMD) / 256, 256>>>();
    k_m<<<dim3(8, NB), 256>>>();
    k_out<<<dim3(NTOT / BM, 4), 256>>>(br, out);
}

// round 6
// speedup vs baseline: 1.4461x; 1.0580x over previous
#include <cuda_runtime.h>
#include <cuda_fp16.h>
#include <cstdint>

#define NB    16
#define NPOS  4096
#define CIN   512
#define DIMD  256
#define NTOT  (NB*NPOS)
#define NSPLIT 8

#define BK 32
#define LDAH 40    // K-major smem row: 32 halves + 8 pad
#define LDBH 136   // MN-major 128-wide row: 128 + 8 pad
#define LDB2H 264  // MN-major 256-wide row: 256 + 8 pad

// stages
#define STG_KM 30720   // A 128x40x2 (10240) + B 256x40x2 (20480)
#define STG_GD 25600   // A 32x136x2 (8704)  + B 32x264x2 (16896)

// ---------------- scratch ----------------
__device__ __half g_qh[(size_t)NTOT*DIMD];
__device__ __half g_kh[(size_t)NTOT*DIMD];
__device__ __half g_vh[(size_t)NTOT*DIMD];
__device__ float g_kmax[NB*DIMD];
__device__ float g_krs [NB*DIMD];
__device__ float g_vmax[NB*DIMD];
__device__ float g_vrs [NB*DIMD];
__device__ float g_gdp[(size_t)NSPLIT*NB*DIMD*DIMD];
__device__ float g_gd [(size_t)NB*DIMD*DIMD];
__device__ __half g_Wth [(size_t)3*DIMD*CIN];  // [which][d=256][k=512]
__device__ __half g_Wrth[(size_t)CIN*DIMD];    // [c=512][d=256]
__device__ __half g_Mth [(size_t)NB*CIN*DIMD]; // [b][c=512][v=256]

// ---------------- helpers ----------------
__device__ __forceinline__ float exp_fast(float x) {
    float t = x * 1.4426950408889634f;
    t = fminf(fmaxf(t, -120.f), 120.f);
    float fi = rintf(t);
    float f  = t - fi;
    float p = 1.3333558146e-3f;
    p = fmaf(p, f, 9.6181291076e-3f);
    p = fmaf(p, f, 5.5504108665e-2f);
    p = fmaf(p, f, 2.4022650696e-1f);
    p = fmaf(p, f, 6.9314718056e-1f);
    p = fmaf(p, f, 1.0f);
    return __int_as_float(((int)fi + 127) << 23) * p;
}
__device__ __forceinline__ uint32_t smem_u32(const void* p) {
    uint32_t a;
    asm("{ .reg .u64 t; cvta.to.shared.u64 t, %1; cvt.u32.u64 %0, t; }" : "=r"(a) : "l"(p));
    return a;
}
__device__ __forceinline__ uint32_t f22h(float a, float b) {
    __half2 h = __floats2half2_rn(a, b);
    return *reinterpret_cast<uint32_t*>(&h);
}
__device__ __forceinline__ void ldsm4(uint32_t (&r)[4], uint32_t addr) {
    asm volatile("ldmatrix.sync.aligned.m8n8.x4.shared.b16 {%0,%1,%2,%3}, [%4];"
        : "=r"(r[0]), "=r"(r[1]), "=r"(r[2]), "=r"(r[3]) : "r"(addr));
}
__device__ __forceinline__ void ldsm4t(uint32_t (&r)[4], uint32_t addr) {
    asm volatile("ldmatrix.sync.aligned.m8n8.x4.trans.shared.b16 {%0,%1,%2,%3}, [%4];"
        : "=r"(r[0]), "=r"(r[1]), "=r"(r[2]), "=r"(r[3]) : "r"(addr));
}
__device__ __forceinline__ void mma16816(float* d, const uint32_t* a, const uint32_t* b) {
    asm volatile(
        "mma.sync.aligned.m16n8k16.row.col.f32.f16.f16.f32 "
        "{%0,%1,%2,%3},{%4,%5,%6,%7},{%8,%9},{%0,%1,%2,%3};"
        : "+f"(d[0]), "+f"(d[1]), "+f"(d[2]), "+f"(d[3])
        : "r"(a[0]), "r"(a[1]), "r"(a[2]), "r"(a[3]), "r"(b[0]), "r"(b[1]));
}
// apply softmax to 8 packed halves (channels base..base+7)
__device__ __forceinline__ void h8_sm(uint4& u, const float* smax, const float* srin, int base) {
    __half2* h = (__half2*)&u;
#pragma unroll
    for (int j = 0; j < 4; j++) {
        float2 f = __half22float2(h[j]);
        f.x = exp_fast(f.x - smax[base + 2*j])     * srin[base + 2*j];
        f.y = exp_fast(f.y - smax[base + 2*j + 1]) * srin[base + 2*j + 1];
        h[j] = __floats2half2_rn(f.x, f.y);
    }
}

// ---------------- loaders (prefetch to regs / store to smem) ----------------
// A K-major 128x32 from f32
__device__ __forceinline__ void pf_A32(const float* __restrict__ s, int ld, float4 (&r)[4]) {
    const int tid = threadIdx.x;
#pragma unroll
    for (int i = 0; i < 4; i++) {
        int idx = tid + i*256, m = idx >> 3, kq = (idx & 7) << 2;
        r[i] = *(const float4*)(s + (size_t)m*ld + kq);
    }
}
__device__ __forceinline__ void st_A32(__half* As, const float4 (&r)[4]) {
    const int tid = threadIdx.x;
#pragma unroll
    for (int i = 0; i < 4; i++) {
        int idx = tid + i*256, m = idx >> 3, kq = (idx & 7) << 2;
        *(uint2*)(As + m*LDAH + kq) = make_uint2(f22h(r[i].x, r[i].y), f22h(r[i].z, r[i].w));
    }
}
// A K-major 128x32 from f16 (with softmax per k-channel)
__device__ __forceinline__ void pf_A16(const __half* __restrict__ s, int ld, uint4 (&r)[2]) {
    const int tid = threadIdx.x;
#pragma unroll
    for (int i = 0; i < 2; i++) {
        int idx = tid + i*256, m = idx >> 2, kq = (idx & 3) << 3;
        r[i] = *(const uint4*)(s + (size_t)m*ld + kq);
    }
}
__device__ __forceinline__ void st_A16_sm(__half* As, uint4 (&r)[2],
                                          const float* smax, const float* srin) {
    const int tid = threadIdx.x;
#pragma unroll
    for (int i = 0; i < 2; i++) {
        int idx = tid + i*256, m = idx >> 2, kq = (idx & 3) << 3;
        h8_sm(r[i], smax, srin, kq);
        *(uint4*)(As + m*LDAH + kq) = r[i];
    }
}
// B K-major 256x32 from f16
__device__ __forceinline__ void pf_B16(const __half* __restrict__ s, int ld, uint4 (&r)[4]) {
    const int tid = threadIdx.x;
#pragma unroll
    for (int i = 0; i < 4; i++) {
        int idx = tid + i*256, n = idx >> 2, kq = (idx & 3) << 3;
        r[i] = *(const uint4*)(s + (size_t)n*ld + kq);
    }
}
__device__ __forceinline__ void st_B16(__half* Bs, const uint4 (&r)[4]) {
    const int tid = threadIdx.x;
#pragma unroll
    for (int i = 0; i < 4; i++) {
        int idx = tid + i*256, n = idx >> 2, kq = (idx & 3) << 3;
        *(uint4*)(Bs + n*LDAH + kq) = r[i];
    }
}
// MN-major 32x128 from f16 (gd A, softmax per v-channel)
__device__ __forceinline__ void pf_T1(const __half* __restrict__ s, int ld, uint4 (&r)[2]) {
    const int tid = threadIdx.x;
#pragma unroll
    for (int i = 0; i < 2; i++) {
        int idx = tid + i*256, k = idx >> 4, nq = (idx & 15) << 3;
        r[i] = *(const uint4*)(s + (size_t)k*ld + nq);
    }
}
__device__ __forceinline__ void st_T1_sm(__half* Ts, uint4 (&r)[2],
                                         const float* smax, const float* srin) {
    const int tid = threadIdx.x;
#pragma unroll
    for (int i = 0; i < 2; i++) {
        int idx = tid + i*256, k = idx >> 4, nq = (idx & 15) << 3;
        h8_sm(r[i], smax, srin, nq);
        *(uint4*)(Ts + k*LDBH + nq) = r[i];
    }
}
// MN-major 32x256 from f16 (gd B)
__device__ __forceinline__ void pf_T2(const __half* __restrict__ s, int ld, uint4 (&r)[4]) {
    const int tid = threadIdx.x;
#pragma unroll
    for (int i = 0; i < 4; i++) {
        int idx = tid + i*256, k = idx >> 5, nq = (idx & 31) << 3;
        r[i] = *(const uint4*)(s + (size_t)k*ld + nq);
    }
}
__device__ __forceinline__ void st_T2(__half* Bs, const uint4 (&r)[4]) {
    const int tid = threadIdx.x;
#pragma unroll
    for (int i = 0; i < 4; i++) {
        int idx = tid + i*256, k = idx >> 5, nq = (idx & 31) << 3;
        *(uint4*)(Bs + k*LDB2H + nq) = r[i];
    }
}

// ---------------- compute: 8 warps 2x4, warp tile 64x64, BN=256 ----------------
__device__ __forceinline__ void compute_256(uint32_t Ab, uint32_t Bb, float (&acc)[4][8][4]) {
    const int lane = threadIdx.x & 31, warp = threadIdx.x >> 5;
    const int wm = (warp >> 2) * 64, wn = (warp & 3) * 64;
#pragma unroll
    for (int kk = 0; kk < 2; kk++) {
        int k0 = kk * 16;
        uint32_t a[4][4], b[8][2];
#pragma unroll
        for (int im = 0; im < 4; im++) {
            int m0 = wm + im * 16;
            ldsm4(a[im], Ab + (((m0 + ((lane>>3)&1)*8 + (lane&7)) * LDAH + k0 + (lane>>4)*8) << 1));
        }
#pragma unroll
        for (int p = 0; p < 4; p++) {
            int n0 = wn + p * 16;
            uint32_t r[4];
            ldsm4(r, Bb + (((n0 + ((lane>>4)&1)*8 + (lane&7)) * LDAH + k0 + ((lane>>3)&1)*8) << 1));
            b[2*p][0]=r[0]; b[2*p][1]=r[1]; b[2*p+1][0]=r[2]; b[2*p+1][1]=r[3];
        }
#pragma unroll
        for (int im = 0; im < 4; im++)
#pragma unroll
            for (int in = 0; in < 8; in++)
                mma16816(acc[im][in], a[im], b[in]);
    }
}
__device__ __forceinline__ void compute_T256(uint32_t Ab, uint32_t Bb, float (&acc)[4][8][4]) {
    const int lane = threadIdx.x & 31, warp = threadIdx.x >> 5;
    const int wm = (warp >> 2) * 64, wn = (warp & 3) * 64;
#pragma unroll
    for (int kk = 0; kk < 2; kk++) {
        int k0 = kk * 16;
        uint32_t a[4][4], b[8][2];
#pragma unroll
        for (int im = 0; im < 4; im++) {
            int m0 = wm + im * 16;
            ldsm4t(a[im], Ab + (((k0 + ((lane>>4)&1)*8 + (lane&7)) * LDBH + m0 + ((lane>>3)&1)*8) << 1));
        }
#pragma unroll
        for (int p = 0; p < 4; p++) {
            int n0 = wn + p * 16;
            uint32_t r[4];
            ldsm4t(r, Bb + (((k0 + ((lane>>3)&1)*8 + (lane&7)) * LDB2H + n0 + ((lane>>4)&1)*8) << 1));
            b[2*p][0]=r[0]; b[2*p][1]=r[1]; b[2*p+1][0]=r[2]; b[2*p+1][1]=r[3];
        }
#pragma unroll
        for (int im = 0; im < 4; im++)
#pragma unroll
            for (int in = 0; in < 8; in++)
                mma16816(acc[im][in], a[im], b[in]);
    }
}
__device__ __forceinline__ void zero_256(float (&acc)[4][8][4]) {
#pragma unroll
    for (int i = 0; i < 4; i++)
#pragma unroll
        for (int j = 0; j < 8; j++)
#pragma unroll
            for (int r = 0; r < 4; r++) acc[i][j][r] = 0.f;
}
__device__ __forceinline__ void epi256_f(float* C, int ldc, float (&acc)[4][8][4],
                                         const float* bias) {
    const int lane = threadIdx.x & 31, warp = threadIdx.x >> 5;
    const int wm = (warp >> 2) * 64, wn = (warp & 3) * 64;
    const int g = lane >> 2, t = lane & 3;
#pragma unroll
    for (int im = 0; im < 4; im++)
#pragma unroll
        for (int in = 0; in < 8; in++) {
            int row = wm + im * 16 + g, col = wn + in * 8 + t * 2;
            float b0 = 0.f, b1 = 0.f;
            if (bias) { b0 = bias[col]; b1 = bias[col + 1]; }
            *(float2*)(C + (size_t)row * ldc + col) =
                make_float2(acc[im][in][0] + b0, acc[im][in][1] + b1);
            *(float2*)(C + (size_t)(row + 8) * ldc + col) =
                make_float2(acc[im][in][2] + b0, acc[im][in][3] + b1);
        }
}
__device__ __forceinline__ void epi256_h(__half* C, int ldc, float (&acc)[4][8][4],
                                         const float* bias) {
    const int lane = threadIdx.x & 31, warp = threadIdx.x >> 5;
    const int wm = (warp >> 2) * 64, wn = (warp & 3) * 64;
    const int g = lane >> 2, t = lane & 3;
#pragma unroll
    for (int im = 0; im < 4; im++)
#pragma unroll
        for (int in = 0; in < 8; in++) {
            int row = wm + im * 16 + g, col = wn + in * 8 + t * 2;
            float b0 = bias[col], b1 = bias[col + 1];
            *(__half2*)(C + (size_t)row * ldc + col) =
                __floats2half2_rn(acc[im][in][0] + b0, acc[im][in][1] + b1);
            *(__half2*)(C + (size_t)(row + 8) * ldc + col) =
                __floats2half2_rn(acc[im][in][2] + b0, acc[im][in][3] + b1);
        }
}

// ---------------- K1: QKV projection (BN=256, double-buffered) ----------------
__global__ __launch_bounds__(256, 1)
void k_proj(const float* __restrict__ x, const float* __restrict__ bq,
            const float* __restrict__ bk, const float* __restrict__ bv) {
    extern __shared__ __align__(16) char smem[];
    int mt = blockIdx.x, which = blockIdx.y;
    const float* bias = (which == 0) ? bq : (which == 1) ? bk : bv;
    __half* out       = (which == 0) ? g_qh : (which == 1) ? g_kh : g_vh;
    const float* Asrc  = x + (size_t)mt * 128 * CIN;
    const __half* Bsrc = g_Wth + (size_t)which * DIMD * CIN;

    float acc[4][8][4];
    zero_256(acc);
    float4 ra[4]; uint4 rb[4];
    pf_A32(Asrc, CIN, ra);
    pf_B16(Bsrc, CIN, rb);
    st_A32((__half*)smem, ra);
    st_B16((__half*)(smem + 10240), rb);
    __syncthreads();
    const int T = CIN / BK;
    for (int i = 0; i < T; i++) {
        char* cur = smem + (i & 1) * STG_KM;
        if (i + 1 < T) {
            pf_A32(Asrc + (i + 1) * BK, CIN, ra);
            pf_B16(Bsrc + (i + 1) * BK, CIN, rb);
        }
        compute_256(smem_u32(cur), smem_u32(cur + 10240), acc);
        if (i + 1 < T) {
            char* nxt = smem + ((i + 1) & 1) * STG_KM;
            st_A32((__half*)nxt, ra);
            st_B16((__half*)(nxt + 10240), rb);
        }
        __syncthreads();
    }
    epi256_h(out + (size_t)mt * 128 * DIMD, DIMD, acc, bias);
}

// ---------------- K2: softmax stats (reads fp16) ----------------
__global__ void k_stats() {
    int bid = blockIdx.x;
    int b = bid >> 4, rem = bid & 15;
    int tensor = rem >> 3, cg = rem & 7;
    const __half* src = tensor ? g_vh : g_kh;
    float* omax = tensor ? g_vmax : g_kmax;
    float* orsm = tensor ? g_vrs : g_krs;
    int tx = threadIdx.x, ty = threadIdx.y;
    int ch = cg * 32 + tx;
    const __half* p = src + (size_t)b * NPOS * DIMD + ch;
    float m = -1e30f, s = 0.f;
    for (int n = ty; n < NPOS; n += 8) {
        float xv = __half2float(p[(size_t)n * DIMD]);
        if (xv > m) { s = s * exp_fast(m - xv) + 1.f; m = xv; }
        else        { s += exp_fast(xv - m); }
    }
    __shared__ float shm[8][32], shs[8][32];
    shm[ty][tx] = m; shs[ty][tx] = s;
    __syncthreads();
    if (ty == 0) {
        float M = shm[0][tx], S = shs[0][tx];
#pragma unroll
        for (int j = 1; j < 8; j++) {
            float mj = shm[j][tx], sj = shs[j][tx];
            float Mn = fmaxf(M, mj);
            S = S * exp_fast(M - Mn) + sj * exp_fast(mj - Mn);
            M = Mn;
        }
        omax[b * DIMD + ch] = M;
        orsm[b * DIMD + ch] = 1.f / S;
    }
}

// ---------------- K3: gd partials (BN=256 trans, double-buffered) ----------------
__global__ __launch_bounds__(256, 1)
void k_gd() {
    extern __shared__ __align__(16) char smem[];
    __shared__ float smax[128], srin[128];
    int bid = blockIdx.x;
    int mt = bid & 1, sp = (bid >> 1) & 7, b = bid >> 4;
    int v0 = mt * 128;
    if (threadIdx.x < 128) {
        smax[threadIdx.x] = g_kmax[b * DIMD + v0 + threadIdx.x];
        srin[threadIdx.x] = g_krs [b * DIMD + v0 + threadIdx.x];
    }
    __syncthreads();
    const __half* Ka = g_kh + (size_t)b * NPOS * DIMD + v0;
    const __half* Qa = g_qh + (size_t)b * NPOS * DIMD;
    const size_t nbase = (size_t)sp * (NPOS / NSPLIT);

    float acc[4][8][4];
    zero_256(acc);
    uint4 ra[2]; uint4 rb[4];
    pf_T1(Ka + nbase * DIMD, DIMD, ra);
    pf_T2(Qa + nbase * DIMD, DIMD, rb);
    st_T1_sm((__half*)smem, ra, smax, srin);
    st_T2((__half*)(smem + 8704), rb);
    __syncthreads();
    const int T = (NPOS / NSPLIT) / BK;
    for (int i = 0; i < T; i++) {
        char* cur = smem + (i & 1) * STG_GD;
        if (i + 1 < T) {
            pf_T1(Ka + (nbase + (i + 1) * BK) * DIMD, DIMD, ra);
            pf_T2(Qa + (nbase + (i + 1) * BK) * DIMD, DIMD, rb);
        }
        compute_T256(smem_u32(cur), smem_u32(cur + 8704), acc);
        if (i + 1 < T) {
            char* nxt = smem + ((i + 1) & 1) * STG_GD;
            st_T1_sm((__half*)nxt, ra, smax, srin);
            st_T2((__half*)(nxt + 8704), rb);
        }
        __syncthreads();
    }
    epi256_f(g_gdp + (((size_t)sp * NB + b) * DIMD + v0) * DIMD, DIMD, acc, nullptr);
}
__global__ void k_gdreduce() {
    size_t i = (size_t)blockIdx.x * blockDim.x + threadIdx.x;
    float s = 0.f;
#pragma unroll
    for (int sp = 0; sp < NSPLIT; sp++)
        s += g_gdp[(size_t)sp * NB * DIMD * DIMD + i];
    g_gd[i] = s;
}

// ---------------- K4: Mth[b][c][v] = Wrt @ gd^T (BN=256, single stage, tiny) ----------------
__global__ __launch_bounds__(256, 1)
void k_m() {
    extern __shared__ __align__(16) char smem[];
    int mt = blockIdx.x, b = blockIdx.y;
    const __half* Asrc = g_Wrth + (size_t)mt * 128 * DIMD;           // [c][d]
    const float*  Bsrc = g_gd + (size_t)b * DIMD * DIMD;             // [v][d]
    __half* As = (__half*)smem;
    __half* Bs = (__half*)(smem + 10240);
    float acc[4][8][4];
    zero_256(acc);
    for (int k0 = 0; k0 < DIMD; k0 += BK) {
        {   // A: 128x32 f16
            uint4 ra[2];
            pf_A16(Asrc + k0, DIMD, ra);
            const int tid = threadIdx.x;
#pragma unroll
            for (int i = 0; i < 2; i++) {
                int idx = tid + i*256, m = idx >> 2, kq = (idx & 3) << 3;
                *(uint4*)(As + m*LDAH + kq) = ra[i];
            }
        }
        {   // B: 256x32 f32 -> f16
            const int tid = threadIdx.x;
#pragma unroll
            for (int i = 0; i < 8; i++) {
                int idx = tid + i*256, n = idx >> 3, kq = (idx & 7) << 2;
                float4 u = *(const float4*)(Bsrc + (size_t)n*DIMD + k0 + kq);
                *(uint2*)(Bs + n*LDAH + kq) = make_uint2(f22h(u.x, u.y), f22h(u.z, u.w));
            }
        }
        __syncthreads();
        compute_256(smem_u32(As), smem_u32(Bs), acc);
        __syncthreads();
    }
    // write half, no bias
    const int lane = threadIdx.x & 31, warp = threadIdx.x >> 5;
    const int wm = (warp >> 2) * 64, wn = (warp & 3) * 64;
    const int g = lane >> 2, t = lane & 3;
    __half* C = g_Mth + ((size_t)b * CIN + mt * 128) * DIMD;
#pragma unroll
    for (int im = 0; im < 4; im++)
#pragma unroll
        for (int in = 0; in < 8; in++) {
            int row = wm + im * 16 + g, col = wn + in * 8 + t * 2;
            *(__half2*)(C + (size_t)row * DIMD + col) =
                __floats2half2_rn(acc[im][in][0], acc[im][in][1]);
            *(__half2*)(C + (size_t)(row + 8) * DIMD + col) =
                __floats2half2_rn(acc[im][in][2], acc[im][in][3]);
        }
}

// ---------------- K5: out = sm(v) @ Mth^T + br (BN=256, double-buffered) ----------------
__global__ __launch_bounds__(256, 1)
void k_out(const float* __restrict__ br, float* __restrict__ out) {
    extern __shared__ __align__(16) char smem[];
    __shared__ float smax[DIMD], srin[DIMD];
    int mt = blockIdx.x, nt = blockIdx.y;
    int b = mt >> 5;
    if (threadIdx.x < DIMD) {
        smax[threadIdx.x] = g_vmax[b * DIMD + threadIdx.x];
        srin[threadIdx.x] = g_vrs [b * DIMD + threadIdx.x];
    }
    __syncthreads();
    const __half* Asrc = g_vh + (size_t)mt * 128 * DIMD;                   // [n][v]
    const __half* Bsrc = g_Mth + ((size_t)b * CIN + nt * 256) * DIMD;      // [c][v]

    float acc[4][8][4];
    zero_256(acc);
    uint4 ra[2]; uint4 rb[4];
    pf_A16(Asrc, DIMD, ra);
    pf_B16(Bsrc, DIMD, rb);
    st_A16_sm((__half*)smem, ra, smax, srin);
    st_B16((__half*)(smem + 10240), rb);
    __syncthreads();
    const int T = DIMD / BK;
    for (int i = 0; i < T; i++) {
        char* cur = smem + (i & 1) * STG_KM;
        if (i + 1 < T) {
            pf_A16(Asrc + (i + 1) * BK, DIMD, ra);
            pf_B16(Bsrc + (i + 1) * BK, DIMD, rb);
        }
        compute_256(smem_u32(cur), smem_u32(cur + 10240), acc);
        if (i + 1 < T) {
            char* nxt = smem + ((i + 1) & 1) * STG_KM;
            st_A16_sm((__half*)nxt, ra, smax + (i + 1) * BK, srin + (i + 1) * BK);
            st_B16((__half*)(nxt + 10240), rb);
        }
        __syncthreads();
    }
    epi256_f(out + (size_t)mt * 128 * CIN + nt * 256, CIN, acc, br + nt * 256);
}

// ---------------- weight transpose + fp16 convert ----------------
__global__ void k_trh(const float* __restrict__ src, __half* __restrict__ dst, int R, int C) {
    __shared__ float t[32][33];
    int bx = blockIdx.x * 32, by = blockIdx.y * 32;
    for (int j = threadIdx.y; j < 32; j += 8)
        t[j][threadIdx.x] = src[(size_t)(by + j) * C + bx + threadIdx.x];
    __syncthreads();
    for (int j = threadIdx.y; j < 32; j += 8)
        dst[(size_t)(bx + j) * R + by + threadIdx.x] = __float2half_rn(t[threadIdx.x][j]);
}

// ---------------- launch ----------------
extern "C" void kernel_launch(void* const* d_in, const int* in_sizes, int n_in,
                              void* d_out, int out_size) {
    (void)in_sizes; (void)n_in; (void)out_size;
    const float* x  = (const float*)d_in[0];
    const float* Wq = (const float*)d_in[1];
    const float* bq = (const float*)d_in[2];
    const float* Wk = (const float*)d_in[3];
    const float* bk = (const float*)d_in[4];
    const float* Wv = (const float*)d_in[5];
    const float* bv = (const float*)d_in[6];
    const float* Wr = (const float*)d_in[7];
    const float* br = (const float*)d_in[8];
    float* out = (float*)d_out;

    static int smem_set = 0;
    if (!smem_set) {
        cudaFuncSetAttribute(k_proj, cudaFuncAttributeMaxDynamicSharedMemorySize, 2 * STG_KM);
        cudaFuncSetAttribute(k_gd,   cudaFuncAttributeMaxDynamicSharedMemorySize, 2 * STG_GD);
        cudaFuncSetAttribute(k_m,    cudaFuncAttributeMaxDynamicSharedMemorySize, STG_KM);
        cudaFuncSetAttribute(k_out,  cudaFuncAttributeMaxDynamicSharedMemorySize, 2 * STG_KM);
        smem_set = 1;
    }

    __half* wt = nullptr; __half* wrt = nullptr;
    cudaGetSymbolAddress((void**)&wt, g_Wth);
    cudaGetSymbolAddress((void**)&wrt, g_Wrth);

    k_trh<<<dim3(8, 16), dim3(32, 8)>>>(Wq, wt, CIN, DIMD);
    k_trh<<<dim3(8, 16), dim3(32, 8)>>>(Wk, wt + (size_t)DIMD * CIN, CIN, DIMD);
    k_trh<<<dim3(8, 16), dim3(32, 8)>>>(Wv, wt + (size_t)2 * DIMD * CIN, CIN, DIMD);
    k_trh<<<dim3(16, 8), dim3(32, 8)>>>(Wr, wrt, DIMD, CIN);

    k_proj<<<dim3(NTOT / 128, 3), 256, 2 * STG_KM>>>(x, bq, bk, bv);
    k_stats<<<NB * 8 * 2, dim3(32, 8)>>>();
    k_gd<<<NB * NSPLIT * 2, 256, 2 * STG_GD>>>();
    k_gdreduce<<<(NB * DIMD * DIMD) / 256, 256>>>();
    k_m<<<dim3(4, NB), 256, STG_KM>>>();
    k_out<<<dim3(NTOT / 128, 2), 256, 2 * STG_KM>>>(br, out);
}